// round 11
// baseline (speedup 1.0000x reference)
#include <cuda_runtime.h>
#include <math.h>

// Problem constants
#define NCLS 6
#define KPP 8
#define NPR 48
#define CDIM 128
#define HH 128
#define WW 128
#define BB 8
#define HORG 512

typedef unsigned long long ull;

// Output layout (flattened tuple, fp32):
//   pred              (8,6,512,512)   ->  0          .. 12582912
//   prototype_expand  (8,48,128)      ->  12582912   .. 12632064
//   p2c_sim_map       (8,48,128,128)  ->  12632064   .. 18923520
//   distance_l2       (8,48,16384)    ->  18923520   .. 25214976
//   proto_new         (48,128)        ->  25214976   .. 25221120

// ---- device scratch (no allocation allowed) ----
__device__ unsigned char g_e[BB * HH * WW];
__device__ float g_centers[BB * 96 * CDIM];
__device__ int   g_nearest[BB * 96];
__device__ float g_proto[NPR * CDIM];
__device__ float g_pn2[NPR];
__device__ float g_pred[BB * NCLS * HH * WW];
__device__ float g_Stot[128 * 128];
__device__ float g_S1[6 * 128 * 128];
__device__ int   g_cnt[128 * 6];

__device__ __forceinline__ float gelu_exact(float x) {
    return 0.5f * x * (1.0f + erff(x * 0.70710678118654752440f));
}
__device__ __forceinline__ float warp_allreduce(float v) {
#pragma unroll
    for (int o = 16; o > 0; o >>= 1) v += __shfl_xor_sync(0xffffffffu, v, o);
    return v;
}
__device__ __forceinline__ ull pack2(float lo, float hi) {
    ull r;
    asm("mov.b64 %0, {%1, %2};" : "=l"(r) : "f"(lo), "f"(hi));
    return r;
}
__device__ __forceinline__ float2 unpk2(ull v) {
    float2 r;
    asm("mov.b64 {%0, %1}, %2;" : "=f"(r.x), "=f"(r.y) : "l"(v));
    return r;
}
__device__ __forceinline__ ull ffma2(ull a, ull b, ull c) {
    ull d;
    asm("fma.rn.f32x2 %0, %1, %2, %3;" : "=l"(d) : "l"(a), "l"(b), "l"(c));
    return d;
}

// ============================================================
// K0: downsampled label map with dtype autodetect (int64 vs int32).
// ============================================================
__global__ void k0_emap(const int* __restrict__ gt32) {
    __shared__ int s_nonzero;
    if (threadIdx.x == 0) s_nonzero = 0;
    __syncthreads();
    for (int t = threadIdx.x; t < 128; t += blockDim.x) {
        if (gt32[t * 16384 + 1] != 0) atomicOr(&s_nonzero, 1);
    }
    __syncthreads();
    int is64 = (s_nonzero == 0);

    int idx = blockIdx.x * blockDim.x + threadIdx.x;
    if (idx >= BB * HH * WW) return;
    int b = idx >> 14;
    int r = idx & 16383;
    int hp = r >> 7;
    int wp = r & 127;
    size_t elem = (size_t)b * 262144 + (size_t)hp * 2048 + (size_t)wp * 4;
    int lab = is64 ? gt32[2 * elem] : gt32[elem];
    g_e[idx] = (lab == 6) ? (unsigned char)0 : (unsigned char)lab;
}

// ============================================================
// K1b: per (b,patch,channel-group): membership bits + masked sums.
// grid (128,4) x 256 threads.
// ============================================================
__global__ void k1b_sums(const float* __restrict__ feats) {
    __shared__ unsigned int mbits[6][32];
    __shared__ int scnt[6];

    int bp = blockIdx.x;
    int g = blockIdx.y;
    int b = bp >> 4;
    int p = bp & 15;
    int nh = p >> 2, nw = p & 3;
    int tid = threadIdx.x;
    int wid = tid >> 5, lane = tid & 31;

    if (tid < 6) scnt[tid] = 0;
    __syncthreads();

#pragma unroll 1
    for (int it = 0; it < 24; it++) {
        int idx = it * 256 + tid;
        int k = idx >> 10;
        int pos = idx & 1023;
        int ph = pos >> 5, pw = pos & 31;
        int n = k * 16384 + (nh * 32 + ph) * 128 + nw * 32 + pw;
        int hp = n / 768;
        int rem = n - hp * 768;
        int wp = rem / 6;
        int kq = rem - wp * 6;
        int m = (g_e[(b << 14) + (hp << 7) + wp] == (unsigned char)kq) ? 1 : 0;
        unsigned bal = __ballot_sync(0xffffffffu, m);
        if (lane == 0) {
            mbits[k][ph] = bal;
            atomicAdd(&scnt[k], __popc(bal));
        }
    }
    __syncthreads();
    if (g == 0 && tid < 6) g_cnt[bp * 6 + tid] = scnt[tid];

    for (int ci = 0; ci < 4; ci++) {
        int c = g * 32 + ci * 8 + wid;
        const float* fptr = feats + (((size_t)(b * 128 + c)) * 128 + nh * 32) * 128 + nw * 32 + lane;
        float at = 0, a0 = 0, a1 = 0, a2 = 0, a3 = 0, a4 = 0, a5 = 0;
#pragma unroll 8
        for (int ph = 0; ph < 32; ph++) {
            float f = fptr[ph * 128];
            at += f;
            if ((mbits[0][ph] >> lane) & 1) a0 += f;
            if ((mbits[1][ph] >> lane) & 1) a1 += f;
            if ((mbits[2][ph] >> lane) & 1) a2 += f;
            if ((mbits[3][ph] >> lane) & 1) a3 += f;
            if ((mbits[4][ph] >> lane) & 1) a4 += f;
            if ((mbits[5][ph] >> lane) & 1) a5 += f;
        }
        at = warp_allreduce(at);
        a0 = warp_allreduce(a0); a1 = warp_allreduce(a1); a2 = warp_allreduce(a2);
        a3 = warp_allreduce(a3); a4 = warp_allreduce(a4); a5 = warp_allreduce(a5);
        if (lane == 0) {
            g_Stot[bp * 128 + c] = at;
            g_S1[0 * 16384 + bp * 128 + c] = a0;
            g_S1[1 * 16384 + bp * 128 + c] = a1;
            g_S1[2 * 16384 + bp * 128 + c] = a2;
            g_S1[3 * 16384 + bp * 128 + c] = a3;
            g_S1[4 * 16384 + bp * 128 + c] = a4;
            g_S1[5 * 16384 + bp * 128 + c] = a5;
        }
    }
}

// ============================================================
// K1c: analytic softmax-context, LN1+GELU, nearest prototype.
// 128 blocks x 192 threads (warp per class).
// ============================================================
__global__ void k1c_centers(const float* __restrict__ prototype,
                            const float* __restrict__ ln1g,
                            const float* __restrict__ ln1b) {
    __shared__ float sproto[48 * 128];
    __shared__ float sp2[48];

    int bp = blockIdx.x;
    int tid = threadIdx.x;
    int wid = tid >> 5, lane = tid & 31;

    for (int idx = tid; idx < 6144; idx += 192) sproto[idx] = prototype[idx];
    __syncthreads();

    for (int j = wid; j < 48; j += 6) {
        float s = 0.f;
#pragma unroll
        for (int i = 0; i < 4; i++) {
            float v = sproto[j * 128 + lane + 32 * i];
            s += v * v;
        }
        s = warp_allreduce(s);
        if (lane == 0) sp2[j] = s;
    }
    __syncthreads();

    int k = wid;
    const float W0 = 0.36787944117144232160f;
    int cnt = g_cnt[bp * 6 + k];
    float denom = (float)cnt + W0 * (float)(1024 - cnt);
    float x[4];
#pragma unroll
    for (int i = 0; i < 4; i++) {
        int c = lane + 32 * i;
        float st = g_Stot[bp * 128 + c];
        float s1 = g_S1[k * 16384 + bp * 128 + c];
        x[i] = (W0 * st + (1.0f - W0) * s1) / denom;
    }
    float s = warp_allreduce(x[0] + x[1] + x[2] + x[3]);
    float mu = s * (1.0f / 128.0f);
    float vs = 0;
#pragma unroll
    for (int i = 0; i < 4; i++) { float d = x[i] - mu; vs += d * d; }
    vs = warp_allreduce(vs);
    float inv = 1.0f / sqrtf(vs * (1.0f / 128.0f) + 1e-6f);
    float g[4];
    float c2p = 0;
#pragma unroll
    for (int i = 0; i < 4; i++) {
        int c = lane + 32 * i;
        float y = (x[i] - mu) * inv * ln1g[c] + ln1b[c];
        float gv = gelu_exact(y);
        g[i] = gv;
        c2p += gv * gv;
        g_centers[((size_t)(bp * 6 + k) << 7) + c] = gv;
    }
    float c2 = warp_allreduce(c2p);
    float best = 3.4e38f;
    int bj = 0;
    for (int j = 0; j < 48; j++) {
        float dp = 0;
#pragma unroll
        for (int i = 0; i < 4; i++) dp += g[i] * sproto[j * 128 + lane + 32 * i];
        float dot = warp_allreduce(dp);
        float d = sqrtf(fmaxf(c2 + sp2[j] - 2.0f * dot, 0.0f));
        if (d < best) { best = d; bj = j; }
    }
    if (lane == 0) g_nearest[bp * 6 + k] = bj;
}

// ============================================================
// K2: per-proto closed-form EMA -- dense, skew-proof.
// 48 blocks x 1024 threads (8 t-groups x 128 channels).
// Warp 0 computes per-center weight w[t] (0 for non-members) via
// ballot ranks; then a dense coalesced weighted sum over all 768
// centers (predication-free, fully independent loads).
// ============================================================
__global__ void __launch_bounds__(1024)
k2_proto(const float* __restrict__ prototype,
         float* __restrict__ out_pnew,
         float* __restrict__ out_pexp) {
    int j = blockIdx.x;
    int tid = threadIdx.x;
    int c = tid & 127;
    int grp = tid >> 7;                 // 0..7
    __shared__ float ws[768];
    __shared__ int s_cnt;
    __shared__ float partial[8][128];
    __shared__ float wsum[4];

    const float L999 = -0.00144349540456856f;   // log2(0.999)

    // warp 0: ranks via ballot prefix (ws[t] = rank for members, -1 else)
    if (tid < 32) {
        int c0 = 0;
        unsigned lt = (1u << tid) - 1u;
#pragma unroll 1
        for (int it = 0; it < 24; it++) {
            int t = it * 32 + tid;
            int m = (g_nearest[t] == j) ? 1 : 0;
            unsigned bal = __ballot_sync(0xffffffffu, m);
            ws[t] = m ? (float)(c0 + __popc(bal & lt)) : -1.0f;
            c0 += __popc(bal);
        }
        if (tid == 0) s_cnt = c0;
    }
    __syncthreads();
    int cnt = s_cnt;
    // ranks -> weights: w = 0.001 * 0.999^(cnt-1-rank), 0 for non-members
    if (tid < 768) {
        float rk = ws[tid];
        ws[tid] = (rk >= 0.0f) ? 0.001f * exp2f(((float)(cnt - 1) - rk) * L999) : 0.0f;
    }
    __syncthreads();

    // dense weighted sum: group grp covers t = grp, grp+8, ... (96 iters)
    float acc = 0.0f;
#pragma unroll 8
    for (int t = grp; t < 768; t += 8)
        acc = fmaf(ws[t], g_centers[(size_t)t * 128 + c], acc);

    partial[grp][c] = acc;
    __syncthreads();

    if (grp == 0) {
        float p0 = prototype[j * 128 + c];
        float a = partial[0][c];
#pragma unroll
        for (int g = 1; g < 8; g++) a += partial[g][c];
        a += exp2f((float)cnt * L999) * p0;
        float pnew = p0 + (a - p0);
        g_proto[j * 128 + c] = pnew;
        out_pnew[j * 128 + c] = pnew;
#pragma unroll
        for (int b = 0; b < 8; b++) out_pexp[b * 6144 + j * 128 + c] = pnew;

        float s = warp_allreduce(pnew * pnew);
        if ((tid & 31) == 0) wsum[tid >> 5] = s;
    }
    __syncthreads();
    if (tid == 0) g_pn2[j] = wsum[0] + wsum[1] + wsum[2] + wsum[3];
}

// ============================================================
// K3: distances to 48 protos (f32x2 FMA), LN2, GELU, class max.
// grid (128,8) x 256 threads; smem ~73KB -> 3 blocks/SM.
// ============================================================
__global__ void __launch_bounds__(256, 3)
k3_dist(const float* __restrict__ feats,
        const float* __restrict__ ln2g,
        const float* __restrict__ ln2b,
        float* __restrict__ out_p2c,
        float* __restrict__ out_dist) {
    extern __shared__ float sm[];
    ull*   spr2 = (ull*)sm;          // [48][128] duplicated (p,p)
    float* sd   = sm + 12288;        // [48][128] x = 1/(1+2d)
    float* sp2  = sm + 18432;
    float* sg2  = sm + 18480;
    float* sb2  = sm + 18528;

    int h = blockIdx.x, b = blockIdx.y;
    int tid = threadIdx.x;
    int wid = tid >> 5, lane = tid & 31;

    for (int idx = tid; idx < 6144; idx += 256) {
        float p = g_proto[idx];
        spr2[idx] = pack2(p, p);
    }
    if (tid < 48) { sp2[tid] = g_pn2[tid]; sg2[tid] = ln2g[tid]; sb2[tid] = ln2b[tid]; }
    __syncthreads();

    int j0 = wid * 6;
    const float4* fp = (const float4*)(feats + ((size_t)b * 128) * 16384 + (size_t)h * 128) + lane;

    ull accA[6], accB[6];
#pragma unroll
    for (int jj = 0; jj < 6; jj++) { accA[jj] = 0ull; accB[jj] = 0ull; }
    ull f2xy = 0ull, f2zw = 0ull;

#pragma unroll 4
    for (int c = 0; c < 128; c++) {
        float4 f = fp[(size_t)c * 4096];
        ull fxy = pack2(f.x, f.y);
        ull fzw = pack2(f.z, f.w);
        f2xy = ffma2(fxy, fxy, f2xy);
        f2zw = ffma2(fzw, fzw, f2zw);
#pragma unroll
        for (int jj = 0; jj < 6; jj++) {
            ull pv = spr2[(j0 + jj) * 128 + c];
            accA[jj] = ffma2(pv, fxy, accA[jj]);
            accB[jj] = ffma2(pv, fzw, accB[jj]);
        }
    }

    float2 f2a = unpk2(f2xy), f2b = unpk2(f2zw);
    int w0 = lane * 4;
#pragma unroll
    for (int jj = 0; jj < 6; jj++) {
        int j = j0 + jj;
        float p2v = sp2[j];
        float2 da = unpk2(accA[jj]), db = unpk2(accB[jj]);
        float4 d;
        d.x = sqrtf(fmaxf(f2a.x + p2v - 2.0f * da.x, 0.0f));
        d.y = sqrtf(fmaxf(f2a.y + p2v - 2.0f * da.y, 0.0f));
        d.z = sqrtf(fmaxf(f2b.x + p2v - 2.0f * db.x, 0.0f));
        d.w = sqrtf(fmaxf(f2b.y + p2v - 2.0f * db.y, 0.0f));
        size_t o = ((size_t)(b * 48 + j) << 14) + (size_t)(h * 128 + w0);
        *reinterpret_cast<float4*>(out_dist + o) = d;
        float4 xv;
        xv.x = 1.0f / (1.0f + 2.0f * d.x);
        xv.y = 1.0f / (1.0f + 2.0f * d.y);
        xv.z = 1.0f / (1.0f + 2.0f * d.z);
        xv.w = 1.0f / (1.0f + 2.0f * d.w);
        ((float4*)sd)[j * 32 + lane] = xv;
    }
    __syncthreads();

    {
        int w = tid >> 1;
        int half = tid & 1;
        int jb = half * 24;
        float xv[24];
        float s = 0;
#pragma unroll
        for (int t = 0; t < 24; t++) {
            xv[t] = sd[(jb + t) * 128 + w];
            s += xv[t];
        }
        s += __shfl_xor_sync(0xffffffffu, s, 1);
        float mu = s * (1.0f / 48.0f);
        float vs = 0;
#pragma unroll
        for (int t = 0; t < 24; t++) { float d = xv[t] - mu; vs += d * d; }
        vs += __shfl_xor_sync(0xffffffffu, vs, 1);
        float inv = 1.0f / sqrtf(vs * (1.0f / 48.0f) + 1e-6f);

        float mx[6];
#pragma unroll
        for (int ncc = 0; ncc < 6; ncc++) mx[ncc] = -3.4e38f;
        size_t ob = ((size_t)(b * 48) << 14) + (size_t)(h * 128 + w);
#pragma unroll
        for (int t = 0; t < 24; t++) {
            int j = jb + t;
            float y = (xv[t] - mu) * inv * sg2[j] + sb2[j];
            float gv = gelu_exact(y);
            out_p2c[ob + ((size_t)j << 14)] = gv;
            int ncc = t % 6;
            mx[ncc] = fmaxf(mx[ncc], gv);
        }
#pragma unroll
        for (int ncc = 0; ncc < 6; ncc++)
            mx[ncc] = fmaxf(mx[ncc], __shfl_xor_sync(0xffffffffu, mx[ncc], 1));
        if (half == 0) {
            size_t pb = ((size_t)(b * 6) << 14) + (size_t)(h * 128 + w);
#pragma unroll
            for (int ncc = 0; ncc < 6; ncc++)
                g_pred[pb + ((size_t)ncc << 14)] = mx[ncc];
        }
    }
}

// ============================================================
// K4: bilinear 128->512 (jax half-pixel centers, edge clamp)
// ============================================================
__global__ void k4_resize(float* __restrict__ out_pred) {
    int idx = blockIdx.x * blockDim.x + threadIdx.x;
    int ox = idx & 511;
    int oy = (idx >> 9) & 511;
    int ch = idx >> 18;
    const float* src = g_pred + ((size_t)ch << 14);
    float sx = (ox + 0.5f) * 0.25f - 0.5f;
    float sy = (oy + 0.5f) * 0.25f - 0.5f;
    float x0f = floorf(sx), y0f = floorf(sy);
    float fx = sx - x0f, fy = sy - y0f;
    int x0 = (int)x0f, y0 = (int)y0f;
    int x0c = max(x0, 0), x1c = min(x0 + 1, 127);
    int y0c = max(y0, 0), y1c = min(y0 + 1, 127);
    float v00 = src[y0c * 128 + x0c], v01 = src[y0c * 128 + x1c];
    float v10 = src[y1c * 128 + x0c], v11 = src[y1c * 128 + x1c];
    float top = v00 + fx * (v01 - v00);
    float bot = v10 + fx * (v11 - v10);
    out_pred[idx] = top + fy * (bot - top);
}

extern "C" void kernel_launch(void* const* d_in, const int* in_sizes, int n_in,
                              void* d_out, int out_size) {
    const float* feats       = (const float*)d_in[0];
    const int*   gt32        = (const int*)d_in[1];
    const float* prototype   = (const float*)d_in[2];
    const float* ln1g        = (const float*)d_in[3];
    const float* ln1b        = (const float*)d_in[4];
    const float* ln2g        = (const float*)d_in[5];
    const float* ln2b        = (const float*)d_in[6];

    float* out = (float*)d_out;
    float* out_pred = out;                    // 12582912
    float* out_pexp = out + 12582912;         // 49152
    float* out_p2c  = out + 12632064;         // 6291456
    float* out_dist = out + 18923520;         // 6291456
    float* out_pnew = out + 25214976;         // 6144

    cudaFuncSetAttribute(k3_dist, cudaFuncAttributeMaxDynamicSharedMemorySize, 18576 * 4);

    k0_emap<<<512, 256>>>(gt32);
    dim3 g1(128, 4);
    k1b_sums<<<g1, 256>>>(feats);
    k1c_centers<<<128, 192>>>(prototype, ln1g, ln1b);
    k2_proto<<<48, 1024>>>(prototype, out_pnew, out_pexp);
    dim3 g3(128, 8);
    k3_dist<<<g3, 256, 18576 * 4>>>(feats, ln2g, ln2b, out_p2c, out_dist);
    k4_resize<<<49152, 256>>>(out_pred);
}

// round 12
// speedup vs baseline: 1.0574x; 1.0574x over previous
#include <cuda_runtime.h>
#include <math.h>

// Problem constants
#define NCLS 6
#define KPP 8
#define NPR 48
#define CDIM 128
#define HH 128
#define WW 128
#define BB 8
#define HORG 512

typedef unsigned long long ull;

// Output layout (flattened tuple, fp32):
//   pred              (8,6,512,512)   ->  0          .. 12582912
//   prototype_expand  (8,48,128)      ->  12582912   .. 12632064
//   p2c_sim_map       (8,48,128,128)  ->  12632064   .. 18923520
//   distance_l2       (8,48,16384)    ->  18923520   .. 25214976
//   proto_new         (48,128)        ->  25214976   .. 25221120

// ---- device scratch (no allocation allowed) ----
__device__ unsigned char g_e[BB * HH * WW];
__device__ float g_centers[BB * 96 * CDIM];
__device__ int   g_nearest[BB * 96];
__device__ float g_proto[NPR * CDIM];
__device__ float g_pn2[NPR];
__device__ float g_pred[BB * NCLS * HH * WW];
__device__ float g_Stot[128 * 128];
__device__ float g_S1[6 * 128 * 128];
__device__ int   g_cnt[128 * 6];

__device__ __forceinline__ float gelu_exact(float x) {
    return 0.5f * x * (1.0f + erff(x * 0.70710678118654752440f));
}
__device__ __forceinline__ float warp_allreduce(float v) {
#pragma unroll
    for (int o = 16; o > 0; o >>= 1) v += __shfl_xor_sync(0xffffffffu, v, o);
    return v;
}
__device__ __forceinline__ ull pack2(float lo, float hi) {
    ull r;
    asm("mov.b64 %0, {%1, %2};" : "=l"(r) : "f"(lo), "f"(hi));
    return r;
}
__device__ __forceinline__ float2 unpk2(ull v) {
    float2 r;
    asm("mov.b64 {%0, %1}, %2;" : "=f"(r.x), "=f"(r.y) : "l"(v));
    return r;
}
__device__ __forceinline__ ull ffma2(ull a, ull b, ull c) {
    ull d;
    asm("fma.rn.f32x2 %0, %1, %2, %3;" : "=l"(d) : "l"(a), "l"(b), "l"(c));
    return d;
}

// ============================================================
// K0: downsampled label map with dtype autodetect (int64 vs int32).
// ============================================================
__global__ void k0_emap(const int* __restrict__ gt32) {
    __shared__ int s_nonzero;
    if (threadIdx.x == 0) s_nonzero = 0;
    __syncthreads();
    for (int t = threadIdx.x; t < 128; t += blockDim.x) {
        if (gt32[t * 16384 + 1] != 0) atomicOr(&s_nonzero, 1);
    }
    __syncthreads();
    int is64 = (s_nonzero == 0);

    int idx = blockIdx.x * blockDim.x + threadIdx.x;
    if (idx >= BB * HH * WW) return;
    int b = idx >> 14;
    int r = idx & 16383;
    int hp = r >> 7;
    int wp = r & 127;
    size_t elem = (size_t)b * 262144 + (size_t)hp * 2048 + (size_t)wp * 4;
    int lab = is64 ? gt32[2 * elem] : gt32[elem];
    g_e[idx] = (lab == 6) ? (unsigned char)0 : (unsigned char)lab;
}

// ============================================================
// K1b: per (b,patch,channel-group): membership bits + masked sums.
// grid (128,4) x 256 threads.
// ============================================================
__global__ void k1b_sums(const float* __restrict__ feats) {
    __shared__ unsigned int mbits[6][32];
    __shared__ int scnt[6];

    int bp = blockIdx.x;
    int g = blockIdx.y;
    int b = bp >> 4;
    int p = bp & 15;
    int nh = p >> 2, nw = p & 3;
    int tid = threadIdx.x;
    int wid = tid >> 5, lane = tid & 31;

    if (tid < 6) scnt[tid] = 0;
    __syncthreads();

#pragma unroll 1
    for (int it = 0; it < 24; it++) {
        int idx = it * 256 + tid;
        int k = idx >> 10;
        int pos = idx & 1023;
        int ph = pos >> 5, pw = pos & 31;
        int n = k * 16384 + (nh * 32 + ph) * 128 + nw * 32 + pw;
        int hp = n / 768;
        int rem = n - hp * 768;
        int wp = rem / 6;
        int kq = rem - wp * 6;
        int m = (g_e[(b << 14) + (hp << 7) + wp] == (unsigned char)kq) ? 1 : 0;
        unsigned bal = __ballot_sync(0xffffffffu, m);
        if (lane == 0) {
            mbits[k][ph] = bal;
            atomicAdd(&scnt[k], __popc(bal));
        }
    }
    __syncthreads();
    if (g == 0 && tid < 6) g_cnt[bp * 6 + tid] = scnt[tid];

    for (int ci = 0; ci < 4; ci++) {
        int c = g * 32 + ci * 8 + wid;
        const float* fptr = feats + (((size_t)(b * 128 + c)) * 128 + nh * 32) * 128 + nw * 32 + lane;
        float at = 0, a0 = 0, a1 = 0, a2 = 0, a3 = 0, a4 = 0, a5 = 0;
#pragma unroll 8
        for (int ph = 0; ph < 32; ph++) {
            float f = fptr[ph * 128];
            at += f;
            if ((mbits[0][ph] >> lane) & 1) a0 += f;
            if ((mbits[1][ph] >> lane) & 1) a1 += f;
            if ((mbits[2][ph] >> lane) & 1) a2 += f;
            if ((mbits[3][ph] >> lane) & 1) a3 += f;
            if ((mbits[4][ph] >> lane) & 1) a4 += f;
            if ((mbits[5][ph] >> lane) & 1) a5 += f;
        }
        at = warp_allreduce(at);
        a0 = warp_allreduce(a0); a1 = warp_allreduce(a1); a2 = warp_allreduce(a2);
        a3 = warp_allreduce(a3); a4 = warp_allreduce(a4); a5 = warp_allreduce(a5);
        if (lane == 0) {
            g_Stot[bp * 128 + c] = at;
            g_S1[0 * 16384 + bp * 128 + c] = a0;
            g_S1[1 * 16384 + bp * 128 + c] = a1;
            g_S1[2 * 16384 + bp * 128 + c] = a2;
            g_S1[3 * 16384 + bp * 128 + c] = a3;
            g_S1[4 * 16384 + bp * 128 + c] = a4;
            g_S1[5 * 16384 + bp * 128 + c] = a5;
        }
    }
}

// ============================================================
// K1c: analytic softmax-context, LN1+GELU, nearest prototype.
// 128 blocks x 192 threads (warp per class).
// ============================================================
__global__ void k1c_centers(const float* __restrict__ prototype,
                            const float* __restrict__ ln1g,
                            const float* __restrict__ ln1b) {
    __shared__ float sproto[48 * 128];
    __shared__ float sp2[48];

    int bp = blockIdx.x;
    int tid = threadIdx.x;
    int wid = tid >> 5, lane = tid & 31;

    for (int idx = tid; idx < 6144; idx += 192) sproto[idx] = prototype[idx];
    __syncthreads();

    for (int j = wid; j < 48; j += 6) {
        float s = 0.f;
#pragma unroll
        for (int i = 0; i < 4; i++) {
            float v = sproto[j * 128 + lane + 32 * i];
            s += v * v;
        }
        s = warp_allreduce(s);
        if (lane == 0) sp2[j] = s;
    }
    __syncthreads();

    int k = wid;
    const float W0 = 0.36787944117144232160f;
    int cnt = g_cnt[bp * 6 + k];
    float denom = (float)cnt + W0 * (float)(1024 - cnt);
    float x[4];
#pragma unroll
    for (int i = 0; i < 4; i++) {
        int c = lane + 32 * i;
        float st = g_Stot[bp * 128 + c];
        float s1 = g_S1[k * 16384 + bp * 128 + c];
        x[i] = (W0 * st + (1.0f - W0) * s1) / denom;
    }
    float s = warp_allreduce(x[0] + x[1] + x[2] + x[3]);
    float mu = s * (1.0f / 128.0f);
    float vs = 0;
#pragma unroll
    for (int i = 0; i < 4; i++) { float d = x[i] - mu; vs += d * d; }
    vs = warp_allreduce(vs);
    float inv = 1.0f / sqrtf(vs * (1.0f / 128.0f) + 1e-6f);
    float g[4];
    float c2p = 0;
#pragma unroll
    for (int i = 0; i < 4; i++) {
        int c = lane + 32 * i;
        float y = (x[i] - mu) * inv * ln1g[c] + ln1b[c];
        float gv = gelu_exact(y);
        g[i] = gv;
        c2p += gv * gv;
        g_centers[((size_t)(bp * 6 + k) << 7) + c] = gv;
    }
    float c2 = warp_allreduce(c2p);
    float best = 3.4e38f;
    int bj = 0;
    for (int j = 0; j < 48; j++) {
        float dp = 0;
#pragma unroll
        for (int i = 0; i < 4; i++) dp += g[i] * sproto[j * 128 + lane + 32 * i];
        float dot = warp_allreduce(dp);
        float d = sqrtf(fmaxf(c2 + sp2[j] - 2.0f * dot, 0.0f));
        if (d < best) { best = d; bj = j; }
    }
    if (lane == 0) g_nearest[bp * 6 + k] = bj;
}

// ============================================================
// K2: per-proto closed-form EMA -- dense, latency-hardened.
// 48 blocks x 1024 threads: thread = (tg 0..31, quad 0..31).
// nearest staged in smem (parallel) -> ballots hit smem;
// main loop: 24 x LDG.128 per thread, 4 independent accs,
// smem tree-reduce over the 32 t-groups.
// ============================================================
__global__ void __launch_bounds__(1024)
k2_proto(const float* __restrict__ prototype,
         float* __restrict__ out_pnew,
         float* __restrict__ out_pexp) {
    int j = blockIdx.x;
    int tid = threadIdx.x;
    int quad = tid & 31;                // channel quad (4 floats)
    int tg = tid >> 5;                  // t-group 0..31
    __shared__ int   snear[768];
    __shared__ float ws[768];
    __shared__ int s_cnt;
    __shared__ float4 part[32][32];     // [tg][quad] 16KB

    const float L999 = -0.00144349540456856f;   // log2(0.999)

    // stage nearest (one parallel coalesced round)
    if (tid < 768) snear[tid] = g_nearest[tid];
    __syncthreads();

    // warp 0: ranks via ballot prefix from smem (fast)
    if (tid < 32) {
        int c0 = 0;
        unsigned lt = (1u << tid) - 1u;
#pragma unroll
        for (int it = 0; it < 24; it++) {
            int t = it * 32 + tid;
            int m = (snear[t] == j) ? 1 : 0;
            unsigned bal = __ballot_sync(0xffffffffu, m);
            ws[t] = m ? (float)(c0 + __popc(bal & lt)) : -1.0f;
            c0 += __popc(bal);
        }
        if (tid == 0) s_cnt = c0;
    }
    __syncthreads();
    int cnt = s_cnt;
    if (tid < 768) {
        float rk = ws[tid];
        ws[tid] = (rk >= 0.0f) ? 0.001f * exp2f(((float)(cnt - 1) - rk) * L999) : 0.0f;
    }
    __syncthreads();

    // dense weighted sum over t: 24 iterations of LDG.128, indep accs
    const float4* cen = (const float4*)g_centers;   // [768][32]
    float ax = 0.f, ay = 0.f, az = 0.f, aw = 0.f;
#pragma unroll 6
    for (int t = tg; t < 768; t += 32) {
        float w = ws[t];
        float4 v = cen[t * 32 + quad];
        ax = fmaf(w, v.x, ax);
        ay = fmaf(w, v.y, ay);
        az = fmaf(w, v.z, az);
        aw = fmaf(w, v.w, aw);
    }
    part[tg][quad] = make_float4(ax, ay, az, aw);
    __syncthreads();

    // tree reduce over tg
#pragma unroll
    for (int s = 16; s >= 1; s >>= 1) {
        if (tg < s) {
            float4 a = part[tg][quad];
            float4 b = part[tg + s][quad];
            part[tg][quad] = make_float4(a.x + b.x, a.y + b.y, a.z + b.z, a.w + b.w);
        }
        __syncthreads();
    }

    // finalize: warp 0 (tg==0), each thread handles 4 channels
    if (tg == 0) {
        float decay = exp2f((float)cnt * L999);
        float4 a = part[0][quad];
        float4 p0 = ((const float4*)prototype)[j * 32 + quad];
        float4 pn;
        pn.x = p0.x + (a.x + decay * p0.x - p0.x);
        pn.y = p0.y + (a.y + decay * p0.y - p0.y);
        pn.z = p0.z + (a.z + decay * p0.z - p0.z);
        pn.w = p0.w + (a.w + decay * p0.w - p0.w);
        ((float4*)g_proto)[j * 32 + quad] = pn;
        ((float4*)out_pnew)[j * 32 + quad] = pn;
#pragma unroll
        for (int b = 0; b < 8; b++)
            ((float4*)out_pexp)[b * 1536 + j * 32 + quad] = pn;
        float s = pn.x * pn.x + pn.y * pn.y + pn.z * pn.z + pn.w * pn.w;
        s = warp_allreduce(s);
        if (quad == 0) g_pn2[j] = s;
    }
}

// ============================================================
// K3: distances to 48 protos (f32x2 FMA), LN2, GELU, class max.
// grid (128,8) x 256 threads; smem ~73KB -> 3 blocks/SM.
// ============================================================
__global__ void __launch_bounds__(256, 3)
k3_dist(const float* __restrict__ feats,
        const float* __restrict__ ln2g,
        const float* __restrict__ ln2b,
        float* __restrict__ out_p2c,
        float* __restrict__ out_dist) {
    extern __shared__ float sm[];
    ull*   spr2 = (ull*)sm;          // [48][128] duplicated (p,p)
    float* sd   = sm + 12288;        // [48][128] x = 1/(1+2d)
    float* sp2  = sm + 18432;
    float* sg2  = sm + 18480;
    float* sb2  = sm + 18528;

    int h = blockIdx.x, b = blockIdx.y;
    int tid = threadIdx.x;
    int wid = tid >> 5, lane = tid & 31;

    for (int idx = tid; idx < 6144; idx += 256) {
        float p = g_proto[idx];
        spr2[idx] = pack2(p, p);
    }
    if (tid < 48) { sp2[tid] = g_pn2[tid]; sg2[tid] = ln2g[tid]; sb2[tid] = ln2b[tid]; }
    __syncthreads();

    int j0 = wid * 6;
    const float4* fp = (const float4*)(feats + ((size_t)b * 128) * 16384 + (size_t)h * 128) + lane;

    ull accA[6], accB[6];
#pragma unroll
    for (int jj = 0; jj < 6; jj++) { accA[jj] = 0ull; accB[jj] = 0ull; }
    ull f2xy = 0ull, f2zw = 0ull;

#pragma unroll 4
    for (int c = 0; c < 128; c++) {
        float4 f = fp[(size_t)c * 4096];
        ull fxy = pack2(f.x, f.y);
        ull fzw = pack2(f.z, f.w);
        f2xy = ffma2(fxy, fxy, f2xy);
        f2zw = ffma2(fzw, fzw, f2zw);
#pragma unroll
        for (int jj = 0; jj < 6; jj++) {
            ull pv = spr2[(j0 + jj) * 128 + c];
            accA[jj] = ffma2(pv, fxy, accA[jj]);
            accB[jj] = ffma2(pv, fzw, accB[jj]);
        }
    }

    float2 f2a = unpk2(f2xy), f2b = unpk2(f2zw);
    int w0 = lane * 4;
#pragma unroll
    for (int jj = 0; jj < 6; jj++) {
        int j = j0 + jj;
        float p2v = sp2[j];
        float2 da = unpk2(accA[jj]), db = unpk2(accB[jj]);
        float4 d;
        d.x = sqrtf(fmaxf(f2a.x + p2v - 2.0f * da.x, 0.0f));
        d.y = sqrtf(fmaxf(f2a.y + p2v - 2.0f * da.y, 0.0f));
        d.z = sqrtf(fmaxf(f2b.x + p2v - 2.0f * db.x, 0.0f));
        d.w = sqrtf(fmaxf(f2b.y + p2v - 2.0f * db.y, 0.0f));
        size_t o = ((size_t)(b * 48 + j) << 14) + (size_t)(h * 128 + w0);
        *reinterpret_cast<float4*>(out_dist + o) = d;
        float4 xv;
        xv.x = 1.0f / (1.0f + 2.0f * d.x);
        xv.y = 1.0f / (1.0f + 2.0f * d.y);
        xv.z = 1.0f / (1.0f + 2.0f * d.z);
        xv.w = 1.0f / (1.0f + 2.0f * d.w);
        ((float4*)sd)[j * 32 + lane] = xv;
    }
    __syncthreads();

    {
        int w = tid >> 1;
        int half = tid & 1;
        int jb = half * 24;
        float xv[24];
        float s = 0;
#pragma unroll
        for (int t = 0; t < 24; t++) {
            xv[t] = sd[(jb + t) * 128 + w];
            s += xv[t];
        }
        s += __shfl_xor_sync(0xffffffffu, s, 1);
        float mu = s * (1.0f / 48.0f);
        float vs = 0;
#pragma unroll
        for (int t = 0; t < 24; t++) { float d = xv[t] - mu; vs += d * d; }
        vs += __shfl_xor_sync(0xffffffffu, vs, 1);
        float inv = 1.0f / sqrtf(vs * (1.0f / 48.0f) + 1e-6f);

        float mx[6];
#pragma unroll
        for (int ncc = 0; ncc < 6; ncc++) mx[ncc] = -3.4e38f;
        size_t ob = ((size_t)(b * 48) << 14) + (size_t)(h * 128 + w);
#pragma unroll
        for (int t = 0; t < 24; t++) {
            int j = jb + t;
            float y = (xv[t] - mu) * inv * sg2[j] + sb2[j];
            float gv = gelu_exact(y);
            out_p2c[ob + ((size_t)j << 14)] = gv;
            int ncc = t % 6;
            mx[ncc] = fmaxf(mx[ncc], gv);
        }
#pragma unroll
        for (int ncc = 0; ncc < 6; ncc++)
            mx[ncc] = fmaxf(mx[ncc], __shfl_xor_sync(0xffffffffu, mx[ncc], 1));
        if (half == 0) {
            size_t pb = ((size_t)(b * 6) << 14) + (size_t)(h * 128 + w);
#pragma unroll
            for (int ncc = 0; ncc < 6; ncc++)
                g_pred[pb + ((size_t)ncc << 14)] = mx[ncc];
        }
    }
}

// ============================================================
// K4: bilinear 128->512 (jax half-pixel centers, edge clamp)
// ============================================================
__global__ void k4_resize(float* __restrict__ out_pred) {
    int idx = blockIdx.x * blockDim.x + threadIdx.x;
    int ox = idx & 511;
    int oy = (idx >> 9) & 511;
    int ch = idx >> 18;
    const float* src = g_pred + ((size_t)ch << 14);
    float sx = (ox + 0.5f) * 0.25f - 0.5f;
    float sy = (oy + 0.5f) * 0.25f - 0.5f;
    float x0f = floorf(sx), y0f = floorf(sy);
    float fx = sx - x0f, fy = sy - y0f;
    int x0 = (int)x0f, y0 = (int)y0f;
    int x0c = max(x0, 0), x1c = min(x0 + 1, 127);
    int y0c = max(y0, 0), y1c = min(y0 + 1, 127);
    float v00 = src[y0c * 128 + x0c], v01 = src[y0c * 128 + x1c];
    float v10 = src[y1c * 128 + x0c], v11 = src[y1c * 128 + x1c];
    float top = v00 + fx * (v01 - v00);
    float bot = v10 + fx * (v11 - v10);
    out_pred[idx] = top + fy * (bot - top);
}

extern "C" void kernel_launch(void* const* d_in, const int* in_sizes, int n_in,
                              void* d_out, int out_size) {
    const float* feats       = (const float*)d_in[0];
    const int*   gt32        = (const int*)d_in[1];
    const float* prototype   = (const float*)d_in[2];
    const float* ln1g        = (const float*)d_in[3];
    const float* ln1b        = (const float*)d_in[4];
    const float* ln2g        = (const float*)d_in[5];
    const float* ln2b        = (const float*)d_in[6];

    float* out = (float*)d_out;
    float* out_pred = out;                    // 12582912
    float* out_pexp = out + 12582912;         // 49152
    float* out_p2c  = out + 12632064;         // 6291456
    float* out_dist = out + 18923520;         // 6291456
    float* out_pnew = out + 25214976;         // 6144

    cudaFuncSetAttribute(k3_dist, cudaFuncAttributeMaxDynamicSharedMemorySize, 18576 * 4);

    k0_emap<<<512, 256>>>(gt32);
    dim3 g1(128, 4);
    k1b_sums<<<g1, 256>>>(feats);
    k1c_centers<<<128, 192>>>(prototype, ln1g, ln1b);
    k2_proto<<<48, 1024>>>(prototype, out_pnew, out_pexp);
    dim3 g3(128, 8);
    k3_dist<<<g3, 256, 18576 * 4>>>(feats, ln2g, ln2b, out_p2c, out_dist);
    k4_resize<<<49152, 256>>>(out_pred);
}